// round 1
// baseline (speedup 1.0000x reference)
#include <cuda_runtime.h>
#include <math.h>

#define TT 128
#define BB 64
#define VV 2048
#define HH 1024
#define GG 4096   // 4*HH
#define EOS_ID 1

// ---------------- scratch (static device allocations) ----------------
__device__ float g_pre[(size_t)TT * BB * GG];   // x @ Wi + b, 134 MB
__device__ float g_gates[BB * GG];              // per-step gate buffer
__device__ float g_c[BB * HH];
__device__ float g_h[BB * HH];
__device__ unsigned char g_eos[TT * BB];        // eos state at ENTRY of step t

// ---------------- helpers ----------------
__device__ __forceinline__ float sigf(float x) { return 1.0f / (1.0f + expf(-x)); }

// ---------------- eos prefix-OR over time (removes eos from recurrence) ----
__global__ void eos_prefix_kernel(const float* __restrict__ x,
                                  const unsigned char* __restrict__ eos0) {
    int b = threadIdx.x;
    if (b >= BB) return;
    unsigned char e = eos0[b] ? 1 : 0;
    for (int t = 0; t < TT; ++t) {
        g_eos[t * BB + b] = e;
        float v = x[((size_t)t * BB + b) * VV + EOS_ID];
        if (v != 0.0f) e = 1;
    }
}

__global__ void init_state_kernel(const float* __restrict__ c0,
                                  const float* __restrict__ h0) {
    int i = blockIdx.x * blockDim.x + threadIdx.x;
    if (i < BB * HH) { g_c[i] = c0[i]; g_h[i] = h0[i]; }
}

// ---------------- Phase 1: g_pre = X(8192x2048) @ Wi(2048x4096) + b ------
// BM=128, BN=64, BK=16, 256 threads, 8x4 microtile per thread.
__global__ void gemm_pre_kernel(const float* __restrict__ A,
                                const float* __restrict__ W,
                                const float* __restrict__ bias) {
    const int BM = 128, BN = 64, BK = 16;
    __shared__ float As[BK][BM];   // transposed: As[k][m]
    __shared__ float Bs[BK][BN];

    int tid = threadIdx.x;                 // 0..255
    int m0 = blockIdx.y * BM;
    int n0 = blockIdx.x * BN;
    int ty = tid / 16;                     // 0..15 -> rows of 8
    int tx = tid % 16;                     // 0..15 -> cols of 4

    float acc[8][4];
#pragma unroll
    for (int i = 0; i < 8; i++)
#pragma unroll
        for (int j = 0; j < 4; j++) acc[i][j] = 0.0f;

    for (int k0 = 0; k0 < VV; k0 += BK) {
        // A tile: 128x16 floats = 512 float4, 2 per thread
#pragma unroll
        for (int q = 0; q < 2; q++) {
            int f4 = tid + q * 256;        // 0..511
            int r  = f4 >> 2;              // 0..127
            int kc = (f4 & 3) << 2;        // 0,4,8,12
            float4 v = *reinterpret_cast<const float4*>(
                &A[(size_t)(m0 + r) * VV + k0 + kc]);
            As[kc + 0][r] = v.x; As[kc + 1][r] = v.y;
            As[kc + 2][r] = v.z; As[kc + 3][r] = v.w;
        }
        // B tile: 16x64 floats = 256 float4, 1 per thread
        {
            int r  = tid >> 4;             // 0..15
            int c4 = (tid & 15) << 2;      // 0..60
            float4 v = *reinterpret_cast<const float4*>(
                &W[(size_t)(k0 + r) * GG + n0 + c4]);
            *reinterpret_cast<float4*>(&Bs[r][c4]) = v;
        }
        __syncthreads();
#pragma unroll
        for (int k = 0; k < BK; k++) {
            float a[8], bv[4];
#pragma unroll
            for (int i = 0; i < 8; i++) a[i] = As[k][ty * 8 + i];
#pragma unroll
            for (int j = 0; j < 4; j++) bv[j] = Bs[k][tx * 4 + j];
#pragma unroll
            for (int i = 0; i < 8; i++)
#pragma unroll
                for (int j = 0; j < 4; j++) acc[i][j] += a[i] * bv[j];
        }
        __syncthreads();
    }

    float b0 = bias[n0 + tx * 4 + 0];
    float b1 = bias[n0 + tx * 4 + 1];
    float b2 = bias[n0 + tx * 4 + 2];
    float b3 = bias[n0 + tx * 4 + 3];
#pragma unroll
    for (int i = 0; i < 8; i++) {
        int row = m0 + ty * 8 + i;
        float4 v;
        v.x = acc[i][0] + b0;
        v.y = acc[i][1] + b1;
        v.z = acc[i][2] + b2;
        v.w = acc[i][3] + b3;
        *reinterpret_cast<float4*>(&g_pre[(size_t)row * GG + n0 + tx * 4]) = v;
    }
}

// ---------------- Recurrent step: g_gates = g_pre[t] + h(64x1024)@Wh(1024x4096)
// BM=64 (full batch), BN=32, BK=16, 128 threads, 4x4 microtile. 128 blocks.
__global__ void gemm_step_kernel(const float* __restrict__ Wh, int t) {
    const int BN = 32, BK = 16;
    __shared__ float As[BK][64];   // h tile, transposed
    __shared__ float Bs[BK][BN];

    int tid = threadIdx.x;         // 0..127
    int n0 = blockIdx.x * BN;
    int ty = tid / 8;              // 0..15 -> rows of 4
    int tx = tid % 8;              // 0..7  -> cols of 4

    const float* pre_t = &g_pre[(size_t)t * BB * GG];

    float acc[4][4];
#pragma unroll
    for (int i = 0; i < 4; i++)
#pragma unroll
        for (int j = 0; j < 4; j++) acc[i][j] = 0.0f;

    for (int k0 = 0; k0 < HH; k0 += BK) {
        // h tile: 64x16 = 256 float4, 2 per thread
#pragma unroll
        for (int q = 0; q < 2; q++) {
            int f4 = tid + q * 128;        // 0..255
            int r  = f4 >> 2;              // 0..63
            int kc = (f4 & 3) << 2;        // 0,4,8,12
            float4 v = *reinterpret_cast<const float4*>(
                &g_h[(size_t)r * HH + k0 + kc]);
            As[kc + 0][r] = v.x; As[kc + 1][r] = v.y;
            As[kc + 2][r] = v.z; As[kc + 3][r] = v.w;
        }
        // Wh tile: 16x32 = 128 float4, 1 per thread
        {
            int r  = tid >> 3;             // 0..15
            int c4 = (tid & 7) << 2;       // 0..28
            float4 v = *reinterpret_cast<const float4*>(
                &Wh[(size_t)(k0 + r) * GG + n0 + c4]);
            *reinterpret_cast<float4*>(&Bs[r][c4]) = v;
        }
        __syncthreads();
#pragma unroll
        for (int k = 0; k < BK; k++) {
            float a[4], bv[4];
#pragma unroll
            for (int i = 0; i < 4; i++) a[i] = As[k][ty * 4 + i];
#pragma unroll
            for (int j = 0; j < 4; j++) bv[j] = Bs[k][tx * 4 + j];
#pragma unroll
            for (int i = 0; i < 4; i++)
#pragma unroll
                for (int j = 0; j < 4; j++) acc[i][j] += a[i] * bv[j];
        }
        __syncthreads();
    }

#pragma unroll
    for (int i = 0; i < 4; i++) {
        int row = ty * 4 + i;
        float4 p = *reinterpret_cast<const float4*>(
            &pre_t[(size_t)row * GG + n0 + tx * 4]);
        float4 v;
        v.x = acc[i][0] + p.x;
        v.y = acc[i][1] + p.y;
        v.z = acc[i][2] + p.z;
        v.w = acc[i][3] + p.w;
        *reinterpret_cast<float4*>(&g_gates[(size_t)row * GG + n0 + tx * 4]) = v;
    }
}

// ---------------- Pointwise LSTM cell + eos masking + output -------------
__global__ void lstm_update_kernel(float* __restrict__ out_t, int t) {
    int idx = blockIdx.x * blockDim.x + threadIdx.x;   // b*HH + j
    if (idx >= BB * HH) return;
    int b = idx / HH;
    int j = idx - b * HH;
    const float* grow = &g_gates[(size_t)b * GG];
    float ig = grow[j];
    float fg = grow[j + HH];
    float gg = grow[j + 2 * HH];
    float og = grow[j + 3 * HH];

    float c = g_c[idx];
    float h = g_h[idx];

    float nc = sigf(fg) * c + sigf(ig) * tanhf(gg);
    float nh = sigf(og) * tanhf(nc);

    out_t[idx] = nh;   // ys collects new_h (UNMASKED), per reference

    unsigned char m = g_eos[t * BB + b];   // eos at entry of step t
    g_c[idx] = m ? c : nc;
    g_h[idx] = m ? h : nh;
}

// ---------------- launch ----------------
extern "C" void kernel_launch(void* const* d_in, const int* in_sizes, int n_in,
                              void* d_out, int out_size) {
    const float* x    = (const float*)d_in[0];
    const float* Wi   = (const float*)d_in[1];
    const float* Wh   = (const float*)d_in[2];
    const float* bias = (const float*)d_in[3];
    const float* c0   = (const float*)d_in[4];
    const float* h0   = (const float*)d_in[5];
    const unsigned char* eos0 = (const unsigned char*)d_in[6];
    float* out = (float*)d_out;

    eos_prefix_kernel<<<1, 64>>>(x, eos0);
    init_state_kernel<<<(BB * HH + 255) / 256, 256>>>(c0, h0);

    // Phase 1: time-parallel input projection (M=8192, N=4096, K=2048)
    gemm_pre_kernel<<<dim3(GG / 64, (TT * BB) / 128), 256>>>(x, Wi, bias);

    // Phase 2: sequential recurrence
    for (int t = 0; t < TT; ++t) {
        gemm_step_kernel<<<GG / 32, 128>>>(Wh, t);
        lstm_update_kernel<<<(BB * HH) / 256, 256>>>(out + (size_t)t * BB * HH, t);
    }
}

// round 2
// speedup vs baseline: 2.8147x; 2.8147x over previous
#include <cuda_runtime.h>
#include <math.h>

#define TT 128
#define BB 64
#define VV 2048
#define HH 1024
#define GG 4096   // 4*HH
#define EOS_ID 1
#define NBLK 128  // persistent recurrence blocks (1 per SM, <=148)

// ---------------- scratch (static device allocations) ----------------
__device__ float g_pre[(size_t)TT * BB * GG];   // x @ Wi + b
__device__ float g_hbuf[2][BB * HH];            // ping-pong h state
__device__ float g_c[BB * HH];
__device__ unsigned char g_eos[TT * BB];        // eos at ENTRY of step t
__device__ unsigned g_bar_count;
__device__ volatile unsigned g_bar_gen;

// ---------------- helpers ----------------
__device__ __forceinline__ float sigf(float x) { return 1.0f / (1.0f + expf(-x)); }

__device__ __forceinline__ unsigned f2tf32(float f) {
    unsigned u; asm("cvt.rna.tf32.f32 %0, %1;" : "=r"(u) : "f"(f)); return u;
}

__device__ __forceinline__ void mma_tf32(float* d,
                                         unsigned a0, unsigned a1, unsigned a2, unsigned a3,
                                         unsigned b0, unsigned b1) {
    asm volatile(
        "mma.sync.aligned.m16n8k8.row.col.f32.tf32.tf32.f32 "
        "{%0,%1,%2,%3}, {%4,%5,%6,%7}, {%8,%9}, {%0,%1,%2,%3};\n"
        : "+f"(d[0]), "+f"(d[1]), "+f"(d[2]), "+f"(d[3])
        : "r"(a0), "r"(a1), "r"(a2), "r"(a3), "r"(b0), "r"(b1));
}

// software grid barrier (all NBLK blocks resident -> safe)
__device__ __forceinline__ void grid_sync() {
    __syncthreads();
    if (threadIdx.x == 0) {
        unsigned my = g_bar_gen;
        __threadfence();
        if (atomicAdd(&g_bar_count, 1) == gridDim.x - 1) {
            atomicExch(&g_bar_count, 0);
            __threadfence();
            g_bar_gen = my + 1;
        } else {
            while (g_bar_gen == my) {}
        }
    }
    __syncthreads();
}

// ---------------- eos prefix-OR over time ----------------
__global__ void eos_prefix_kernel(const float* __restrict__ x,
                                  const unsigned char* __restrict__ eos0) {
    int b = threadIdx.x;
    if (b >= BB) return;
    unsigned char e = eos0[b] ? 1 : 0;
#pragma unroll 8
    for (int t = 0; t < TT; ++t) {
        g_eos[t * BB + b] = e;
        float v = x[((size_t)t * BB + b) * VV + EOS_ID];
        if (v != 0.0f) e = 1;
    }
}

// ---------------- Phase 1: g_pre = X(8192x2048) @ Wi(2048x4096) + b (tf32) ----
// 128x128x32 tile, 256 threads (8 warps in 2x4), 16 m16n8k8 tiles per warp.
__global__ void __launch_bounds__(256) gemm_pre_tf32(
        const float* __restrict__ A,
        const float* __restrict__ W,
        const float* __restrict__ bias) {
    __shared__ unsigned As[128][36];   // [m][k], pad 4
    __shared__ unsigned Bs[32][136];   // [k][n], pad 8

    const int tid = threadIdx.x;
    const int w = tid >> 5, lane = tid & 31;
    const int m0blk = blockIdx.y * 128;
    const int n0blk = blockIdx.x * 128;
    const int wm = (w >> 2) * 64;      // warp m base within tile
    const int wn = (w & 3) * 32;      // warp n base within tile
    const int r = lane >> 2, kq = lane & 3;

    float acc[16][4];
#pragma unroll
    for (int i = 0; i < 16; i++)
#pragma unroll
        for (int j = 0; j < 4; j++) acc[i][j] = 0.0f;

    float4 ra[4], rb[4];

    // prefetch first tile (k0 = 0)
#pragma unroll
    for (int q = 0; q < 4; ++q) {
        int f4 = tid + q * 256;                 // 0..1023
        int row = f4 >> 3, c4 = (f4 & 7) << 2;  // A: 128 rows x 8 float4
        ra[q] = *reinterpret_cast<const float4*>(&A[(size_t)(m0blk + row) * VV + c4]);
        int rowB = f4 >> 5, c4B = (f4 & 31) << 2; // B: 32 rows x 32 float4
        rb[q] = *reinterpret_cast<const float4*>(&W[(size_t)rowB * GG + n0blk + c4B]);
    }
#pragma unroll
    for (int q = 0; q < 4; ++q) {
        int f4 = tid + q * 256;
        int row = f4 >> 3, c4 = (f4 & 7) << 2;
        uint4 ua = make_uint4(f2tf32(ra[q].x), f2tf32(ra[q].y), f2tf32(ra[q].z), f2tf32(ra[q].w));
        *reinterpret_cast<uint4*>(&As[row][c4]) = ua;
        int rowB = f4 >> 5, c4B = (f4 & 31) << 2;
        uint4 ub = make_uint4(f2tf32(rb[q].x), f2tf32(rb[q].y), f2tf32(rb[q].z), f2tf32(rb[q].w));
        *reinterpret_cast<uint4*>(&Bs[rowB][c4B]) = ub;
    }
    __syncthreads();

    for (int k0 = 0; k0 < VV; k0 += 32) {
        bool more = (k0 + 32 < VV);
        if (more) {
#pragma unroll
            for (int q = 0; q < 4; ++q) {
                int f4 = tid + q * 256;
                int row = f4 >> 3, c4 = (f4 & 7) << 2;
                ra[q] = *reinterpret_cast<const float4*>(
                    &A[(size_t)(m0blk + row) * VV + k0 + 32 + c4]);
                int rowB = f4 >> 5, c4B = (f4 & 31) << 2;
                rb[q] = *reinterpret_cast<const float4*>(
                    &W[(size_t)(k0 + 32 + rowB) * GG + n0blk + c4B]);
            }
        }
        // compute 4 k-steps
#pragma unroll
        for (int ks = 0; ks < 4; ++ks) {
            int kk = ks * 8;
            unsigned af[4][4];
#pragma unroll
            for (int mt = 0; mt < 4; ++mt) {
                int mb = wm + mt * 16;
                af[mt][0] = As[mb + r][kk + kq];
                af[mt][1] = As[mb + r + 8][kk + kq];
                af[mt][2] = As[mb + r][kk + kq + 4];
                af[mt][3] = As[mb + r + 8][kk + kq + 4];
            }
            unsigned bf[4][2];
#pragma unroll
            for (int nt = 0; nt < 4; ++nt) {
                int nb = wn + nt * 8;
                bf[nt][0] = Bs[kk + kq][nb + r];
                bf[nt][1] = Bs[kk + kq + 4][nb + r];
            }
#pragma unroll
            for (int mt = 0; mt < 4; ++mt)
#pragma unroll
                for (int nt = 0; nt < 4; ++nt)
                    mma_tf32(acc[mt * 4 + nt],
                             af[mt][0], af[mt][1], af[mt][2], af[mt][3],
                             bf[nt][0], bf[nt][1]);
        }
        __syncthreads();
        if (more) {
#pragma unroll
            for (int q = 0; q < 4; ++q) {
                int f4 = tid + q * 256;
                int row = f4 >> 3, c4 = (f4 & 7) << 2;
                uint4 ua = make_uint4(f2tf32(ra[q].x), f2tf32(ra[q].y), f2tf32(ra[q].z), f2tf32(ra[q].w));
                *reinterpret_cast<uint4*>(&As[row][c4]) = ua;
                int rowB = f4 >> 5, c4B = (f4 & 31) << 2;
                uint4 ub = make_uint4(f2tf32(rb[q].x), f2tf32(rb[q].y), f2tf32(rb[q].z), f2tf32(rb[q].w));
                *reinterpret_cast<uint4*>(&Bs[rowB][c4B]) = ub;
            }
            __syncthreads();
        }
    }

    // epilogue: add bias, store fp32
#pragma unroll
    for (int mt = 0; mt < 4; ++mt) {
#pragma unroll
        for (int nt = 0; nt < 4; ++nt) {
            float* a = acc[mt * 4 + nt];
            int col = n0blk + wn + nt * 8 + 2 * kq;
            float b0 = bias[col], b1 = bias[col + 1];
            int row0 = m0blk + wm + mt * 16 + r;
            float2 v0 = make_float2(a[0] + b0, a[1] + b1);
            float2 v1 = make_float2(a[2] + b0, a[3] + b1);
            *reinterpret_cast<float2*>(&g_pre[(size_t)row0 * GG + col]) = v0;
            *reinterpret_cast<float2*>(&g_pre[(size_t)(row0 + 8) * GG + col]) = v1;
        }
    }
}

// ---------------- Phase 2: persistent recurrence --------------------------
// 128 blocks x 256 threads. Block owns 8 h-cols; Wh slice [4][1024][8] lives
// in smem (tf32) for all 128 steps. h ping-pongs in global via L2 (ldcg/stcg).
// Warps 0-3: m-tiles (16 batches each) x all 4 gates, K in [0,512).
// Warps 4-7: same tiles, K in [512,1024); reduced via smem. One grid barrier/step.
__global__ void __launch_bounds__(256) lstm_recurrent(
        const float* __restrict__ Wh,
        const float* __restrict__ h0,
        const float* __restrict__ c0,
        float* __restrict__ out) {
    extern __shared__ unsigned smem[];
    unsigned* sWh = smem;                          // [g][k][n] : g*8192 + k*8 + n
    unsigned* sH  = smem + 4 * 1024 * 8;           // [64][132]
    float*   sRed = (float*)(smem + 4 * 1024 * 8 + 64 * 132); // [16][32][4]

    const int tid = threadIdx.x;
    const int w = tid >> 5, lane = tid & 31;
    const int blk = blockIdx.x;
    const int j0 = blk * 8;

    // load + convert Wh slice once
    for (int i = tid; i < 4 * 1024 * 8; i += 256) {
        int n = i & 7;
        int k = (i >> 3) & 1023;
        int g = i >> 13;
        sWh[i] = f2tf32(Wh[(size_t)k * GG + g * HH + j0 + n]);
    }
    // init own columns of h, c
    for (int i = tid; i < BB * 8; i += 256) {
        int b = i >> 3, n = i & 7;
        g_hbuf[0][b * HH + j0 + n] = h0[b * HH + j0 + n];
        g_c[b * HH + j0 + n] = c0[b * HH + j0 + n];
    }
    grid_sync();

    const int half = w >> 2;      // 0: K[0,512)  1: K[512,1024)
    const int mt = w & 3;
    const int m0 = mt * 16;
    const int r = lane >> 2;      // 0..7
    const int kq = lane & 3;

    for (int t = 0; t < TT; ++t) {
        float acc[4][4];
#pragma unroll
        for (int g = 0; g < 4; ++g)
#pragma unroll
            for (int j = 0; j < 4; ++j) acc[g][j] = 0.0f;

        const float* hin = g_hbuf[t & 1];
        float* hout = g_hbuf[(t + 1) & 1];

        for (int c = 0; c < 8; ++c) {
            __syncthreads();
            // stage h chunk [64 x 128] (cols c*128..) into smem as tf32
#pragma unroll
            for (int q = 0; q < 8; ++q) {
                int f4 = tid + q * 256;            // 0..2047
                int row = f4 >> 5;
                int c4 = (f4 & 31) << 2;
                float4 v = __ldcg(reinterpret_cast<const float4*>(
                    &hin[row * HH + c * 128 + c4]));
                uint4 u = make_uint4(f2tf32(v.x), f2tf32(v.y), f2tf32(v.z), f2tf32(v.w));
                *reinterpret_cast<uint4*>(&sH[row * 132 + c4]) = u;
            }
            __syncthreads();
#pragma unroll
            for (int ks = 0; ks < 8; ++ks) {
                int kk = (half * 8 + ks) * 8;      // 0..120 within chunk
                unsigned a0 = sH[(m0 + r) * 132 + kk + kq];
                unsigned a1 = sH[(m0 + r + 8) * 132 + kk + kq];
                unsigned a2 = sH[(m0 + r) * 132 + kk + kq + 4];
                unsigned a3 = sH[(m0 + r + 8) * 132 + kk + kq + 4];
                int kglob = c * 128 + kk;
#pragma unroll
                for (int g = 0; g < 4; ++g) {
                    unsigned b0 = sWh[g * 8192 + (kglob + kq) * 8 + r];
                    unsigned b1 = sWh[g * 8192 + (kglob + kq + 4) * 8 + r];
                    mma_tf32(acc[g], a0, a1, a2, a3, b0, b1);
                }
            }
        }
        __syncthreads();
        if (half == 1) {
#pragma unroll
            for (int g = 0; g < 4; ++g)
                *reinterpret_cast<float4*>(&sRed[((mt * 4 + g) * 32 + lane) * 4]) =
                    make_float4(acc[g][0], acc[g][1], acc[g][2], acc[g][3]);
        }
        __syncthreads();
        if (half == 0) {
#pragma unroll
            for (int g = 0; g < 4; ++g) {
                float4 v = *reinterpret_cast<float4*>(&sRed[((mt * 4 + g) * 32 + lane) * 4]);
                acc[g][0] += v.x; acc[g][1] += v.y; acc[g][2] += v.z; acc[g][3] += v.w;
            }
            const float* pre_t = g_pre + (size_t)t * BB * GG;
            const unsigned char* eos_t = g_eos + t * BB;
#pragma unroll
            for (int p = 0; p < 4; ++p) {
                int row = m0 + r + ((p >= 2) ? 8 : 0);
                int col = 2 * kq + (p & 1);
                int j = j0 + col;
                const float* prow = pre_t + (size_t)row * GG;
                float iv = acc[0][p] + prow[j];
                float fv = acc[1][p] + prow[HH + j];
                float gv = acc[2][p] + prow[2 * HH + j];
                float ov = acc[3][p] + prow[3 * HH + j];
                float cold = g_c[row * HH + j];
                float nc = sigf(fv) * cold + sigf(iv) * tanhf(gv);
                float nh = sigf(ov) * tanhf(nc);
                out[(size_t)t * BB * HH + row * HH + j] = nh;
                unsigned char m = eos_t[row];
                g_c[row * HH + j] = m ? cold : nc;
                float hold = __ldcg(&hin[row * HH + j]);
                __stcg(&hout[row * HH + j], m ? hold : nh);
            }
        }
        grid_sync();
    }
}

// ---------------- launch ----------------
extern "C" void kernel_launch(void* const* d_in, const int* in_sizes, int n_in,
                              void* d_out, int out_size) {
    const float* x    = (const float*)d_in[0];
    const float* Wi   = (const float*)d_in[1];
    const float* Wh   = (const float*)d_in[2];
    const float* bias = (const float*)d_in[3];
    const float* c0   = (const float*)d_in[4];
    const float* h0   = (const float*)d_in[5];
    const unsigned char* eos0 = (const unsigned char*)d_in[6];
    float* out = (float*)d_out;

    eos_prefix_kernel<<<1, 64>>>(x, eos0);

    // Phase 1: time-parallel input projection (tf32 tensor cores)
    gemm_pre_tf32<<<dim3(GG / 128, (TT * BB) / 128), 256>>>(x, Wi, bias);

    // Phase 2: persistent recurrence (one kernel for all 128 steps)
    const int smem_bytes = (4 * 1024 * 8 + 64 * 132) * 4 + 16 * 32 * 4 * 4; // 173056
    cudaFuncSetAttribute(lstm_recurrent,
                         cudaFuncAttributeMaxDynamicSharedMemorySize, smem_bytes);
    lstm_recurrent<<<NBLK, 256, smem_bytes>>>(Wh, h0, c0, out);
}

// round 3
// speedup vs baseline: 3.0500x; 1.0836x over previous
#include <cuda_runtime.h>
#include <cstdint>
#include <math.h>

#define TT 128
#define BB 64
#define VV 2048
#define HH 1024
#define GG 4096   // 4*HH
#define EOS_ID 1
#define NBLK 128

// ---------------- scratch ----------------
__device__ unsigned g_xt[(size_t)TT * BB * VV];    // x as tf32 bits
__device__ unsigned g_wit[(size_t)GG * VV];        // Wi^T [n][k] as tf32 bits
__device__ float    g_pre[(size_t)TT * BB * GG];   // x@Wi + b (fp32)
__device__ unsigned g_hbuf[2][BB * HH];            // h state as tf32 bits (ping-pong)
__device__ float    g_c[BB * HH];
__device__ unsigned char g_eos[TT * BB];
__device__ unsigned g_bar_count;
__device__ volatile unsigned g_bar_gen;

// ---------------- helpers ----------------
__device__ __forceinline__ float sigf(float x) { return 1.0f / (1.0f + expf(-x)); }

__device__ __forceinline__ unsigned f2tf32(float f) {
    unsigned u; asm("cvt.rna.tf32.f32 %0, %1;" : "=r"(u) : "f"(f)); return u;
}

__device__ __forceinline__ void mma_tf32(float* d,
                                         unsigned a0, unsigned a1, unsigned a2, unsigned a3,
                                         unsigned b0, unsigned b1) {
    asm volatile(
        "mma.sync.aligned.m16n8k8.row.col.f32.tf32.tf32.f32 "
        "{%0,%1,%2,%3}, {%4,%5,%6,%7}, {%8,%9}, {%0,%1,%2,%3};\n"
        : "+f"(d[0]), "+f"(d[1]), "+f"(d[2]), "+f"(d[3])
        : "r"(a0), "r"(a1), "r"(a2), "r"(a3), "r"(b0), "r"(b1));
}

__device__ __forceinline__ uint32_t sptr(const void* p) {
    return (uint32_t)__cvta_generic_to_shared(p);
}

__device__ __forceinline__ void cp16(uint32_t saddr, const void* g) {
    asm volatile("cp.async.cg.shared.global [%0], [%1], 16;" :: "r"(saddr), "l"(g));
}
__device__ __forceinline__ void cp_commit() { asm volatile("cp.async.commit_group;"); }
template <int N> __device__ __forceinline__ void cp_wait() {
    asm volatile("cp.async.wait_group %0;" :: "n"(N));
}

__device__ __forceinline__ void ldsm4(unsigned& r0, unsigned& r1, unsigned& r2, unsigned& r3,
                                      uint32_t addr) {
    asm volatile("ldmatrix.sync.aligned.m8n8.x4.shared.b16 {%0,%1,%2,%3}, [%4];"
                 : "=r"(r0), "=r"(r1), "=r"(r2), "=r"(r3) : "r"(addr));
}

__device__ __forceinline__ void grid_sync() {
    __threadfence();
    __syncthreads();
    if (threadIdx.x == 0) {
        unsigned my = g_bar_gen;
        if (atomicAdd(&g_bar_count, 1) == gridDim.x - 1) {
            atomicExch(&g_bar_count, 0);
            __threadfence();
            g_bar_gen = my + 1;
        } else {
            while (g_bar_gen == my) {}
        }
    }
    __syncthreads();
}

// ---------------- preconvert x -> tf32 bits ----------------
__global__ void conv_x_kernel(const float* __restrict__ x) {
    size_t i = ((size_t)blockIdx.x * blockDim.x + threadIdx.x) * 4;
    float4 v = *reinterpret_cast<const float4*>(x + i);
    uint4 u = make_uint4(f2tf32(v.x), f2tf32(v.y), f2tf32(v.z), f2tf32(v.w));
    *reinterpret_cast<uint4*>(g_xt + i) = u;
}

// ---------------- transpose + convert Wi[k][n] -> g_wit[n][k] -------------
__global__ void transp_wi_kernel(const float* __restrict__ Wi) {
    __shared__ unsigned tile[32][33];
    int n0 = blockIdx.x * 32;   // n tile
    int k0 = blockIdx.y * 32;   // k tile
    int tx = threadIdx.x, ty = threadIdx.y;
#pragma unroll
    for (int i = ty; i < 32; i += 8)
        tile[i][tx] = f2tf32(Wi[(size_t)(k0 + i) * GG + n0 + tx]);
    __syncthreads();
#pragma unroll
    for (int i = ty; i < 32; i += 8)
        g_wit[(size_t)(n0 + i) * VV + k0 + tx] = tile[tx][i];
}

// ---------------- Phase 1: tf32 GEMM with cp.async + ldmatrix -------------
// 128x128x32 tile, 256 threads (8 warps in 2x4), warp tile 64x32.
#define P1S 4608   // 128*36 words per operand stage
__global__ void __launch_bounds__(256) gemm_pre_tc(const float* __restrict__ bias) {
    extern __shared__ unsigned sm1[];
    unsigned* As[2] = { sm1,            sm1 + 2 * P1S };
    unsigned* Bs[2] = { sm1 + P1S,      sm1 + 3 * P1S };

    const int tid = threadIdx.x;
    const int w = tid >> 5, lane = tid & 31;
    const int m0blk = blockIdx.y * 128;
    const int n0blk = blockIdx.x * 128;
    const int wm = (w >> 2) * 64;
    const int wn = (w & 3) * 32;
    const int r = lane >> 2, kq = lane & 3;

    // ldmatrix lane address components
    const int a_row = (lane & 7) + (lane & 8);          // 0..15
    const int a_kof = (lane >> 4) << 2;                 // 0 or 4
    const int b_part = lane >> 3;
    const int b_row = ((b_part >> 1) << 3) + (lane & 7); // 0..15
    const int b_kof = (b_part & 1) << 2;                 // 0 or 4

    float acc[16][4];
#pragma unroll
    for (int i = 0; i < 16; i++)
#pragma unroll
        for (int j = 0; j < 4; j++) acc[i][j] = 0.0f;

    const int row8 = tid >> 3, cc8 = (tid & 7) << 2;    // loader coords

    // prologue: stage 0
#pragma unroll
    for (int q = 0; q < 4; ++q) {
        int row = row8 + q * 32;
        cp16(sptr(&As[0][row * 36 + cc8]), g_xt + (size_t)(m0blk + row) * VV + cc8);
        cp16(sptr(&Bs[0][row * 36 + cc8]), g_wit + (size_t)(n0blk + row) * VV + cc8);
    }
    cp_commit();

    for (int it = 0; it < VV / 32; ++it) {
        int nxt = it + 1;
        if (nxt < VV / 32) {
            int s = nxt & 1;
            int k0 = nxt * 32;
#pragma unroll
            for (int q = 0; q < 4; ++q) {
                int row = row8 + q * 32;
                cp16(sptr(&As[s][row * 36 + cc8]), g_xt + (size_t)(m0blk + row) * VV + k0 + cc8);
                cp16(sptr(&Bs[s][row * 36 + cc8]), g_wit + (size_t)(n0blk + row) * VV + k0 + cc8);
            }
            cp_commit();
            cp_wait<1>();
        } else {
            cp_wait<0>();
        }
        __syncthreads();

        const unsigned* Ab = As[it & 1];
        const unsigned* Bb = Bs[it & 1];
#pragma unroll
        for (int ks = 0; ks < 4; ++ks) {
            int kk = ks * 8;
            unsigned af[4][4];
#pragma unroll
            for (int mt = 0; mt < 4; ++mt) {
                uint32_t ad = sptr(Ab + (wm + mt * 16 + a_row) * 36 + kk + a_kof);
                ldsm4(af[mt][0], af[mt][1], af[mt][2], af[mt][3], ad);
            }
            unsigned bf[4][2];
            {
                uint32_t bd0 = sptr(Bb + (wn + b_row) * 36 + kk + b_kof);
                unsigned q0, q1, q2, q3;
                ldsm4(q0, q1, q2, q3, bd0);
                bf[0][0] = q0; bf[0][1] = q1; bf[1][0] = q2; bf[1][1] = q3;
                uint32_t bd1 = sptr(Bb + (wn + 16 + b_row) * 36 + kk + b_kof);
                ldsm4(q0, q1, q2, q3, bd1);
                bf[2][0] = q0; bf[2][1] = q1; bf[3][0] = q2; bf[3][1] = q3;
            }
#pragma unroll
            for (int mt = 0; mt < 4; ++mt)
#pragma unroll
                for (int nt = 0; nt < 4; ++nt)
                    mma_tf32(acc[mt * 4 + nt],
                             af[mt][0], af[mt][1], af[mt][2], af[mt][3],
                             bf[nt][0], bf[nt][1]);
        }
        __syncthreads();
    }

    // epilogue
#pragma unroll
    for (int mt = 0; mt < 4; ++mt) {
#pragma unroll
        for (int nt = 0; nt < 4; ++nt) {
            float* a = acc[mt * 4 + nt];
            int col = n0blk + wn + nt * 8 + 2 * kq;
            float b0 = __ldg(&bias[col]), b1 = __ldg(&bias[col + 1]);
            int row0 = m0blk + wm + mt * 16 + r;
            *reinterpret_cast<float2*>(&g_pre[(size_t)row0 * GG + col]) =
                make_float2(a[0] + b0, a[1] + b1);
            *reinterpret_cast<float2*>(&g_pre[(size_t)(row0 + 8) * GG + col]) =
                make_float2(a[2] + b0, a[3] + b1);
        }
    }
}

// ---------------- Phase 2: persistent recurrence --------------------------
// smem words: sWh 32768 | sH[2] 2*8448 | sRed 2048  -> 206848 bytes
__global__ void __launch_bounds__(256) lstm_recurrent(
        const float* __restrict__ Wh,
        const float* __restrict__ h0,
        const float* __restrict__ c0,
        const float* __restrict__ x,
        const unsigned char* __restrict__ eos0,
        float* __restrict__ out) {
    extern __shared__ unsigned sm2[];
    unsigned* sWh = sm2;
    unsigned* sH[2] = { sm2 + 32768, sm2 + 32768 + 8448 };
    float* sRed = (float*)(sm2 + 32768 + 16896);

    const int tid = threadIdx.x;
    const int w = tid >> 5, lane = tid & 31;
    const int blk = blockIdx.x;
    const int j0 = blk * 8;

    // ---- prologue ----
    if (blk == 0) {  // eos prefix-OR
        unsigned char* flags = (unsigned char*)sRed;
        for (int i = tid; i < TT * BB; i += 256) {
            int t = i >> 6, b = i & 63;
            flags[i] = (x[((size_t)t * BB + b) * VV + EOS_ID] != 0.0f) ? 1 : 0;
        }
        __syncthreads();
        if (tid < BB) {
            unsigned char e = eos0[tid] ? 1 : 0;
            for (int t = 0; t < TT; ++t) {
                g_eos[t * BB + tid] = e;
                e |= flags[t * BB + tid];
            }
        }
        __syncthreads();
    }
    // Wh slice -> smem, pair-interleaved: word = g*8192 + (k>>3)*64 + (k&3)*16 + n*2 + ((k>>2)&1)
    for (int i = tid; i < 4 * 1024 * 8; i += 256) {
        int n = i & 7;
        int k = (i >> 3) & 1023;
        int g = i >> 13;
        float v = Wh[(size_t)k * GG + g * HH + j0 + n];
        sWh[g * 8192 + (k >> 3) * 64 + (k & 3) * 16 + n * 2 + ((k >> 2) & 1)] = f2tf32(v);
    }
    // own columns of h (tf32 bits), c
    for (int i = tid; i < BB * 8; i += 256) {
        int b = i >> 3, n = i & 7;
        g_hbuf[0][b * HH + j0 + n] = f2tf32(h0[b * HH + j0 + n]);
        g_c[b * HH + j0 + n] = c0[b * HH + j0 + n];
    }
    grid_sync();

    const int half = w >> 2;
    const int mt = w & 3;
    const int m0 = mt * 16;
    const int r = lane >> 2;
    const int kq = lane & 3;
    const int a_row = (lane & 7) + (lane & 8);
    const int a_kof = (lane >> 4) << 2;
    const int row5 = tid >> 5, cc5 = (tid & 31) << 2;  // stage loader coords

    for (int t = 0; t < TT; ++t) {
        const unsigned* hin = g_hbuf[t & 1];
        unsigned* hout = g_hbuf[(t + 1) & 1];

        // stage chunk 0
#pragma unroll
        for (int q = 0; q < 8; ++q) {
            int row = row5 + q * 8;
            cp16(sptr(&sH[0][row * 132 + cc5]), hin + (size_t)row * HH + cc5);
        }
        cp_commit();

        float acc[4][4];
#pragma unroll
        for (int g = 0; g < 4; ++g)
#pragma unroll
            for (int j = 0; j < 4; ++j) acc[g][j] = 0.0f;

        for (int c = 0; c < 8; ++c) {
            if (c < 7) {
                unsigned* dst = sH[(c + 1) & 1];
                const unsigned* src = hin + (c + 1) * 128;
#pragma unroll
                for (int q = 0; q < 8; ++q) {
                    int row = row5 + q * 8;
                    cp16(sptr(&dst[row * 132 + cc5]), src + (size_t)row * HH + cc5);
                }
                cp_commit();
                cp_wait<1>();
            } else {
                cp_wait<0>();
            }
            __syncthreads();

            const unsigned* sh = sH[c & 1];
#pragma unroll
            for (int ks = 0; ks < 8; ++ks) {
                int colb = half * 64 + ks * 8;
                unsigned a0, a1, a2, a3;
                ldsm4(a0, a1, a2, a3, sptr(sh + (m0 + a_row) * 132 + colb + a_kof));
                int kk8 = c * 16 + half * 8 + ks;
                const unsigned* wb = sWh + kk8 * 64 + kq * 16 + r * 2;
#pragma unroll
                for (int g = 0; g < 4; ++g) {
                    uint2 bb = *reinterpret_cast<const uint2*>(wb + g * 8192);
                    mma_tf32(acc[g], a0, a1, a2, a3, bb.x, bb.y);
                }
            }
            __syncthreads();
        }

        if (half == 1) {
#pragma unroll
            for (int g = 0; g < 4; ++g)
                *reinterpret_cast<float4*>(&sRed[((mt * 4 + g) * 32 + lane) * 4]) =
                    make_float4(acc[g][0], acc[g][1], acc[g][2], acc[g][3]);
        }
        __syncthreads();
        if (half == 0) {
#pragma unroll
            for (int g = 0; g < 4; ++g) {
                float4 v = *reinterpret_cast<float4*>(&sRed[((mt * 4 + g) * 32 + lane) * 4]);
                acc[g][0] += v.x; acc[g][1] += v.y; acc[g][2] += v.z; acc[g][3] += v.w;
            }
            const float* pre_t = g_pre + (size_t)t * BB * GG;
            const unsigned char* eos_t = g_eos + t * BB;
#pragma unroll
            for (int p = 0; p < 4; ++p) {
                int row = m0 + r + ((p >= 2) ? 8 : 0);
                int col = 2 * kq + (p & 1);
                int j = j0 + col;
                const float* prow = pre_t + (size_t)row * GG;
                float iv = acc[0][p] + __ldcg(&prow[j]);
                float fv = acc[1][p] + __ldcg(&prow[HH + j]);
                float gv = acc[2][p] + __ldcg(&prow[2 * HH + j]);
                float ov = acc[3][p] + __ldcg(&prow[3 * HH + j]);
                float cold = g_c[row * HH + j];
                float nc = sigf(fv) * cold + sigf(iv) * tanhf(gv);
                float nh = sigf(ov) * tanhf(nc);
                __stcg(&out[(size_t)t * BB * HH + row * HH + j], nh);
                unsigned char m = eos_t[row];
                g_c[row * HH + j] = m ? cold : nc;
                unsigned hold = hin[row * HH + j];
                hout[row * HH + j] = m ? hold : f2tf32(nh);
            }
        }
        grid_sync();
    }
}

// ---------------- launch ----------------
extern "C" void kernel_launch(void* const* d_in, const int* in_sizes, int n_in,
                              void* d_out, int out_size) {
    const float* x    = (const float*)d_in[0];
    const float* Wi   = (const float*)d_in[1];
    const float* Wh   = (const float*)d_in[2];
    const float* bias = (const float*)d_in[3];
    const float* c0   = (const float*)d_in[4];
    const float* h0   = (const float*)d_in[5];
    const unsigned char* eos0 = (const unsigned char*)d_in[6];
    float* out = (float*)d_out;

    conv_x_kernel<<<(TT * BB * VV) / (256 * 4), 256>>>(x);
    transp_wi_kernel<<<dim3(GG / 32, VV / 32), dim3(32, 8)>>>(Wi);

    static int inited = 0;
    const int p1_smem = 4 * P1S * 4;                      // 73728
    const int p2_smem = (32768 + 16896 + 2048) * 4;       // 206848
    if (!inited) {
        cudaFuncSetAttribute(gemm_pre_tc,
                             cudaFuncAttributeMaxDynamicSharedMemorySize, p1_smem);
        cudaFuncSetAttribute(lstm_recurrent,
                             cudaFuncAttributeMaxDynamicSharedMemorySize, p2_smem);
        inited = 1;
    }
    gemm_pre_tc<<<dim3(GG / 128, (TT * BB) / 128), 256, p1_smem>>>(bias);
    lstm_recurrent<<<NBLK, 256, p2_smem>>>(Wh, h0, c0, x, eos0, out);
}

// round 4
// speedup vs baseline: 4.7620x; 1.5613x over previous
#include <cuda_runtime.h>
#include <cuda_fp16.h>
#include <cstdint>
#include <math.h>

#define TT 128
#define BB 64
#define VV 2048
#define HH 1024
#define GG 4096   // 4*HH
#define EOS_ID 1
#define NBLK 128

// ---------------- scratch ----------------
__device__ __half g_xh[(size_t)TT * BB * VV];      // x as fp16
__device__ __half g_wih[(size_t)GG * VV];          // Wi^T [n][k] as fp16
__device__ float  g_pre[(size_t)TT * BB * GG];     // x@Wi + b (fp32)
__device__ __half g_hbuf[2][BB * HH];              // h state fp16 (ping-pong)
__device__ float  g_c[BB * HH];
__device__ unsigned char g_eos[TT * BB];
__device__ unsigned g_bar_count;
__device__ volatile unsigned g_bar_gen;

// ---------------- helpers ----------------
__device__ __forceinline__ float sigf(float x) { return 1.0f / (1.0f + expf(-x)); }

__device__ __forceinline__ void mma_f16(float* d,
                                        unsigned a0, unsigned a1, unsigned a2, unsigned a3,
                                        unsigned b0, unsigned b1) {
    asm volatile(
        "mma.sync.aligned.m16n8k16.row.col.f32.f16.f16.f32 "
        "{%0,%1,%2,%3}, {%4,%5,%6,%7}, {%8,%9}, {%0,%1,%2,%3};\n"
        : "+f"(d[0]), "+f"(d[1]), "+f"(d[2]), "+f"(d[3])
        : "r"(a0), "r"(a1), "r"(a2), "r"(a3), "r"(b0), "r"(b1));
}

__device__ __forceinline__ uint32_t sptr(const void* p) {
    return (uint32_t)__cvta_generic_to_shared(p);
}
__device__ __forceinline__ void cp16(uint32_t saddr, const void* g) {
    asm volatile("cp.async.cg.shared.global [%0], [%1], 16;" :: "r"(saddr), "l"(g));
}
__device__ __forceinline__ void cp_commit() { asm volatile("cp.async.commit_group;"); }
template <int N> __device__ __forceinline__ void cp_wait() {
    asm volatile("cp.async.wait_group %0;" :: "n"(N));
}
__device__ __forceinline__ void ldsm4(unsigned& r0, unsigned& r1, unsigned& r2, unsigned& r3,
                                      uint32_t addr) {
    asm volatile("ldmatrix.sync.aligned.m8n8.x4.shared.b16 {%0,%1,%2,%3}, [%4];"
                 : "=r"(r0), "=r"(r1), "=r"(r2), "=r"(r3) : "r"(addr));
}

__device__ __forceinline__ void grid_sync() {
    __threadfence();
    __syncthreads();
    if (threadIdx.x == 0) {
        unsigned my = g_bar_gen;
        if (atomicAdd(&g_bar_count, 1) == gridDim.x - 1) {
            atomicExch(&g_bar_count, 0);
            __threadfence();
            g_bar_gen = my + 1;
        } else {
            while (g_bar_gen == my) {}
        }
    }
    __syncthreads();
}

// ---------------- preconvert x -> fp16 ----------------
__global__ void conv_x_kernel(const float* __restrict__ x) {
    size_t i = ((size_t)blockIdx.x * blockDim.x + threadIdx.x) * 8;
    float4 v0 = *reinterpret_cast<const float4*>(x + i);
    float4 v1 = *reinterpret_cast<const float4*>(x + i + 4);
    __half2 h0 = __floats2half2_rn(v0.x, v0.y);
    __half2 h1 = __floats2half2_rn(v0.z, v0.w);
    __half2 h2 = __floats2half2_rn(v1.x, v1.y);
    __half2 h3 = __floats2half2_rn(v1.z, v1.w);
    uint4 u;
    u.x = *(unsigned*)&h0; u.y = *(unsigned*)&h1;
    u.z = *(unsigned*)&h2; u.w = *(unsigned*)&h3;
    *reinterpret_cast<uint4*>(&g_xh[i]) = u;
}

// ---------------- transpose + convert Wi[k][n] -> g_wih[n][k] fp16 --------
__global__ void transp_wi_kernel(const float* __restrict__ Wi) {
    __shared__ __half tile[32][33];
    int n0 = blockIdx.x * 32;
    int k0 = blockIdx.y * 32;
    int tx = threadIdx.x, ty = threadIdx.y;
#pragma unroll
    for (int i = ty; i < 32; i += 8)
        tile[i][tx] = __float2half_rn(Wi[(size_t)(k0 + i) * GG + n0 + tx]);
    __syncthreads();
#pragma unroll
    for (int i = ty; i < 32; i += 8)
        g_wih[(size_t)(n0 + i) * VV + k0 + tx] = tile[tx][i];
}

// ---------------- Phase 1: fp16 GEMM, 128x128x64, 256 threads -------------
// smem halfs: As0 @0, Bs0 @9216, As1 @18432, Bs1 @27648  (rows padded to 72)
__global__ void __launch_bounds__(256) gemm_pre_tc(const float* __restrict__ bias) {
    extern __shared__ __half sm1[];
    __half* As[2] = { sm1,          sm1 + 18432 };
    __half* Bs[2] = { sm1 + 9216,   sm1 + 27648 };

    const int tid = threadIdx.x;
    const int w = tid >> 5, lane = tid & 31;
    const int m0blk = blockIdx.y * 128;
    const int n0blk = blockIdx.x * 128;
    const int wm = (w >> 2) * 64;
    const int wn = (w & 3) * 32;
    const int r = lane >> 2, kq = lane & 3;

    // ldmatrix address components
    const int a_row = (lane & 7) + (lane & 8);          // 0..15
    const int a_k8  = (lane >> 4) << 3;                 // 0 or 8 (halfs)
    const int b_nrow = (lane & 7) + ((lane >> 4) << 3); // 0..15
    const int b_k8   = ((lane >> 3) & 1) << 3;          // 0 or 8

    float acc[16][4];
#pragma unroll
    for (int i = 0; i < 16; i++)
#pragma unroll
        for (int j = 0; j < 4; j++) acc[i][j] = 0.0f;

    const int lrow = tid >> 3, lc16 = (tid & 7) << 3;   // loader: row 0..31(+q*32), col halfs

    // prologue stage 0
#pragma unroll
    for (int q = 0; q < 4; ++q) {
        int row = lrow + q * 32;
        cp16(sptr(&As[0][row * 72 + lc16]), g_xh + (size_t)(m0blk + row) * VV + lc16);
        cp16(sptr(&Bs[0][row * 72 + lc16]), g_wih + (size_t)(n0blk + row) * VV + lc16);
    }
    cp_commit();

    const int NIT = VV / 64;
    for (int it = 0; it < NIT; ++it) {
        int nxt = it + 1;
        if (nxt < NIT) {
            int s = nxt & 1;
            int k0 = nxt * 64;
#pragma unroll
            for (int q = 0; q < 4; ++q) {
                int row = lrow + q * 32;
                cp16(sptr(&As[s][row * 72 + lc16]),
                     g_xh + (size_t)(m0blk + row) * VV + k0 + lc16);
                cp16(sptr(&Bs[s][row * 72 + lc16]),
                     g_wih + (size_t)(n0blk + row) * VV + k0 + lc16);
            }
            cp_commit();
            cp_wait<1>();
        } else {
            cp_wait<0>();
        }
        __syncthreads();

        const __half* Ab = As[it & 1];
        const __half* Bb = Bs[it & 1];
#pragma unroll
        for (int ks = 0; ks < 4; ++ks) {
            int kk = ks * 16;
            unsigned af[4][4];
#pragma unroll
            for (int mt = 0; mt < 4; ++mt)
                ldsm4(af[mt][0], af[mt][1], af[mt][2], af[mt][3],
                      sptr(Ab + (wm + mt * 16 + a_row) * 72 + kk + a_k8));
            unsigned bf[4][2];
            {
                unsigned q0, q1, q2, q3;
                ldsm4(q0, q1, q2, q3, sptr(Bb + (wn + b_nrow) * 72 + kk + b_k8));
                bf[0][0] = q0; bf[0][1] = q1; bf[1][0] = q2; bf[1][1] = q3;
                ldsm4(q0, q1, q2, q3, sptr(Bb + (wn + 16 + b_nrow) * 72 + kk + b_k8));
                bf[2][0] = q0; bf[2][1] = q1; bf[3][0] = q2; bf[3][1] = q3;
            }
#pragma unroll
            for (int mt = 0; mt < 4; ++mt)
#pragma unroll
                for (int nt = 0; nt < 4; ++nt)
                    mma_f16(acc[mt * 4 + nt],
                            af[mt][0], af[mt][1], af[mt][2], af[mt][3],
                            bf[nt][0], bf[nt][1]);
        }
        __syncthreads();
    }

    // epilogue: add bias, store fp32
#pragma unroll
    for (int mt = 0; mt < 4; ++mt) {
#pragma unroll
        for (int nt = 0; nt < 4; ++nt) {
            float* a = acc[mt * 4 + nt];
            int col = n0blk + wn + nt * 8 + 2 * kq;
            float b0 = __ldg(&bias[col]), b1 = __ldg(&bias[col + 1]);
            int row0 = m0blk + wm + mt * 16 + r;
            *reinterpret_cast<float2*>(&g_pre[(size_t)row0 * GG + col]) =
                make_float2(a[0] + b0, a[1] + b1);
            *reinterpret_cast<float2*>(&g_pre[(size_t)(row0 + 8) * GG + col]) =
                make_float2(a[2] + b0, a[3] + b1);
        }
    }
}

// ---------------- Phase 2: persistent recurrence (fp16) -------------------
// smem bytes: sWh2 uint2[4][64][32] = 65536 | sH0/sH1 half[64*520] = 66560 ea
//             | sRed float[2048] = 8192   -> total 206848
__global__ void __launch_bounds__(256) lstm_recurrent(
        const float* __restrict__ Wh,
        const float* __restrict__ h0,
        const float* __restrict__ c0,
        const float* __restrict__ x,
        const unsigned char* __restrict__ eos0,
        float* __restrict__ out) {
    extern __shared__ unsigned char sm2[];
    uint2*  sWh2 = (uint2*)sm2;                              // 65536 B
    __half* sH[2] = { (__half*)(sm2 + 65536),
                      (__half*)(sm2 + 65536 + 66560) };
    float*  sRed = (float*)(sm2 + 65536 + 2 * 66560);

    const int tid = threadIdx.x;
    const int w = tid >> 5, lane = tid & 31;
    const int blk = blockIdx.x;
    const int j0 = blk * 8;

    // ---- prologue ----
    if (blk == 0) {  // eos prefix-OR
        unsigned char* flags = (unsigned char*)sRed;
        for (int i = tid; i < TT * BB; i += 256) {
            int t = i >> 6, b = i & 63;
            flags[i] = (x[((size_t)t * BB + b) * VV + EOS_ID] != 0.0f) ? 1 : 0;
        }
        __syncthreads();
        if (tid < BB) {
            unsigned char e = eos0[tid] ? 1 : 0;
            for (int t = 0; t < TT; ++t) {
                g_eos[t * BB + tid] = e;
                e |= flags[t * BB + tid];
            }
        }
        __syncthreads();
    }
    // Wh -> smem as pre-built B fragments: sWh2[g*2048 + kk16*32 + lane]
    for (int i = tid; i < 4 * 64 * 32; i += 256) {
        int t = i & 31;
        int kk = (i >> 5) & 63;
        int g = i >> 11;
        int k0 = kk * 16 + (t & 3) * 2;
        int n = t >> 2;
        const float* wp = Wh + (size_t)k0 * GG + g * HH + j0 + n;
        __half2 lo = __floats2half2_rn(wp[0], wp[GG]);
        __half2 hi = __floats2half2_rn(wp[8 * GG], wp[9 * GG]);
        sWh2[i] = make_uint2(*(unsigned*)&lo, *(unsigned*)&hi);
    }
    // own columns of h (fp16), c (fp32)
    for (int i = tid; i < BB * 8; i += 256) {
        int b = i >> 3, n = i & 7;
        g_hbuf[0][b * HH + j0 + n] = __float2half_rn(h0[b * HH + j0 + n]);
        g_c[b * HH + j0 + n] = c0[b * HH + j0 + n];
    }
    grid_sync();

    const int half_w = w >> 2;       // K-half within chunk
    const int mt = w & 3;
    const int m0 = mt * 16;
    const int r = lane >> 2;
    const int kq = lane & 3;
    const int a_row = (lane & 7) + (lane & 8);
    const int a_k8 = (lane >> 4) << 3;
    const int lrow = tid >> 2, lc16 = (tid & 3) << 3;   // loader: row 0..63, col base

    for (int t = 0; t < TT; ++t) {
        const __half* hin = g_hbuf[t & 1];
        __half* hout = g_hbuf[(t + 1) & 1];

        // stage both 512-col chunks up front (16 cp16/thread per chunk)
#pragma unroll
        for (int c = 0; c < 2; ++c) {
            __half* dst = sH[c];
            const __half* src = hin + c * 512;
#pragma unroll
            for (int q = 0; q < 16; ++q) {
                int col = lc16 + q * 32;   // halfs 0..511
                cp16(sptr(&dst[lrow * 520 + col]), src + (size_t)lrow * HH + col);
            }
            cp_commit();
        }

        float acc[4][4];
#pragma unroll
        for (int g = 0; g < 4; ++g)
#pragma unroll
            for (int j = 0; j < 4; ++j) acc[g][j] = 0.0f;

#pragma unroll
        for (int c = 0; c < 2; ++c) {
            if (c == 0) cp_wait<1>(); else cp_wait<0>();
            __syncthreads();
            const __half* sh = sH[c];
#pragma unroll
            for (int ks = 0; ks < 16; ++ks) {
                int kloc = half_w * 256 + ks * 16;
                unsigned a0, a1, a2, a3;
                ldsm4(a0, a1, a2, a3, sptr(sh + (m0 + a_row) * 520 + kloc + a_k8));
                int kk16 = c * 32 + half_w * 16 + ks;
                const uint2* wb = sWh2 + kk16 * 32 + lane;
#pragma unroll
                for (int g = 0; g < 4; ++g) {
                    uint2 bb = wb[g * 2048];
                    mma_f16(acc[g], a0, a1, a2, a3, bb.x, bb.y);
                }
            }
            if (c == 0) __syncthreads();
        }

        __syncthreads();
        if (half_w == 1) {
#pragma unroll
            for (int g = 0; g < 4; ++g)
                *reinterpret_cast<float4*>(&sRed[((mt * 4 + g) * 32 + lane) * 4]) =
                    make_float4(acc[g][0], acc[g][1], acc[g][2], acc[g][3]);
        }
        __syncthreads();
        if (half_w == 0) {
#pragma unroll
            for (int g = 0; g < 4; ++g) {
                float4 v = *reinterpret_cast<float4*>(&sRed[((mt * 4 + g) * 32 + lane) * 4]);
                acc[g][0] += v.x; acc[g][1] += v.y; acc[g][2] += v.z; acc[g][3] += v.w;
            }
            const float* pre_t = g_pre + (size_t)t * BB * GG;
            const unsigned char* eos_t = g_eos + t * BB;
#pragma unroll
            for (int p = 0; p < 4; ++p) {
                int row = m0 + r + ((p >= 2) ? 8 : 0);
                int col = 2 * kq + (p & 1);
                int j = j0 + col;
                const float* prow = pre_t + (size_t)row * GG;
                float iv = acc[0][p] + __ldcg(&prow[j]);
                float fv = acc[1][p] + __ldcg(&prow[HH + j]);
                float gv = acc[2][p] + __ldcg(&prow[2 * HH + j]);
                float ov = acc[3][p] + __ldcg(&prow[3 * HH + j]);
                float cold = g_c[row * HH + j];
                float nc = sigf(fv) * cold + sigf(iv) * tanhf(gv);
                float nh = sigf(ov) * tanhf(nc);
                __stcg(&out[(size_t)t * BB * HH + row * HH + j], nh);
                unsigned char m = eos_t[row];
                g_c[row * HH + j] = m ? cold : nc;
                __half hold = hin[row * HH + j];
                hout[row * HH + j] = m ? hold : __float2half_rn(nh);
            }
        }
        grid_sync();
    }
}

// ---------------- launch ----------------
extern "C" void kernel_launch(void* const* d_in, const int* in_sizes, int n_in,
                              void* d_out, int out_size) {
    const float* x    = (const float*)d_in[0];
    const float* Wi   = (const float*)d_in[1];
    const float* Wh   = (const float*)d_in[2];
    const float* bias = (const float*)d_in[3];
    const float* c0   = (const float*)d_in[4];
    const float* h0   = (const float*)d_in[5];
    const unsigned char* eos0 = (const unsigned char*)d_in[6];
    float* out = (float*)d_out;

    conv_x_kernel<<<(TT * BB * VV) / (256 * 8), 256>>>(x);
    transp_wi_kernel<<<dim3(GG / 32, VV / 32), dim3(32, 8)>>>(Wi);

    static int inited = 0;
    const int p1_smem = 4 * 9216 * 2;                 // 73728
    const int p2_smem = 65536 + 2 * 66560 + 8192;     // 206848
    if (!inited) {
        cudaFuncSetAttribute(gemm_pre_tc,
                             cudaFuncAttributeMaxDynamicSharedMemorySize, p1_smem);
        cudaFuncSetAttribute(lstm_recurrent,
                             cudaFuncAttributeMaxDynamicSharedMemorySize, p2_smem);
        inited = 1;
    }
    gemm_pre_tc<<<dim3(GG / 128, (TT * BB) / 128), 256, p1_smem>>>(bias);
    lstm_recurrent<<<NBLK, 256, p2_smem>>>(Wh, h0, c0, x, eos0, out);
}

// round 7
// speedup vs baseline: 5.0743x; 1.0656x over previous
#include <cuda_runtime.h>
#include <cuda_fp16.h>
#include <cstdint>
#include <math.h>

#define TT 128
#define BB 64
#define VV 2048
#define HH 1024
#define GG 4096   // 4*HH
#define EOS_ID 1
#define NBLK 128

// ---------------- scratch ----------------
__device__ __half g_xh[(size_t)TT * BB * VV];      // x as fp16
__device__ __half g_wih[(size_t)GG * VV];          // Wi^T [n][k] as fp16
__device__ float  g_pre[(size_t)TT * BB * GG];     // x@Wi + b (fp32)
__device__ __half g_hbuf[2][BB * HH];              // h state fp16 (ping-pong)
__device__ float  g_c[BB * HH];
__device__ unsigned char g_eos[TT * BB];
// hierarchical barrier state
__device__ unsigned g_cnt[8];
__device__ unsigned g_root;
__device__ volatile unsigned g_gen;

// ---------------- helpers ----------------
__device__ __forceinline__ float sigf(float x) { return 1.0f / (1.0f + expf(-x)); }

__device__ __forceinline__ uint32_t sptr(const void* p) {
    return (uint32_t)__cvta_generic_to_shared(p);
}
__device__ __forceinline__ void cp16(uint32_t saddr, const void* g) {
    asm volatile("cp.async.cg.shared.global [%0], [%1], 16;" :: "r"(saddr), "l"(g));
}
__device__ __forceinline__ void cp_commit() { asm volatile("cp.async.commit_group;"); }
template <int N> __device__ __forceinline__ void cp_wait() {
    asm volatile("cp.async.wait_group %0;" :: "n"(N));
}
__device__ __forceinline__ void ldsm4(unsigned& r0, unsigned& r1, unsigned& r2, unsigned& r3,
                                      uint32_t addr) {
    asm volatile("ldmatrix.sync.aligned.m8n8.x4.shared.b16 {%0,%1,%2,%3}, [%4];"
                 : "=r"(r0), "=r"(r1), "=r"(r2), "=r"(r3) : "r"(addr));
}
__device__ __forceinline__ void mma_f16(float* d,
                                        unsigned a0, unsigned a1, unsigned a2, unsigned a3,
                                        unsigned b0, unsigned b1) {
    asm volatile(
        "mma.sync.aligned.m16n8k16.row.col.f32.f16.f16.f32 "
        "{%0,%1,%2,%3}, {%4,%5,%6,%7}, {%8,%9}, {%0,%1,%2,%3};\n"
        : "+f"(d[0]), "+f"(d[1]), "+f"(d[2]), "+f"(d[3])
        : "r"(a0), "r"(a1), "r"(a2), "r"(a3), "r"(b0), "r"(b1));
}

// hierarchical grid barrier: 8 groups of 16 blocks -> 8-way root
__device__ __forceinline__ void grid_sync() {
    __threadfence();
    __syncthreads();
    if (threadIdx.x == 0) {
        unsigned my = g_gen;
        int grp = blockIdx.x >> 4;
        if (atomicAdd(&g_cnt[grp], 1) == 15) {
            if (atomicAdd(&g_root, 1) == 7) {
                g_root = 0;
#pragma unroll
                for (int i = 0; i < 8; ++i) g_cnt[i] = 0;
                __threadfence();
                g_gen = my + 1;
            }
        }
        while (g_gen == my) {}
    }
    __syncthreads();
}

// ---------------- preconvert x -> fp16 ----------------
__global__ void conv_x_kernel(const float* __restrict__ x) {
    size_t i = ((size_t)blockIdx.x * blockDim.x + threadIdx.x) * 8;
    float4 v0 = *reinterpret_cast<const float4*>(x + i);
    float4 v1 = *reinterpret_cast<const float4*>(x + i + 4);
    __half2 h0 = __floats2half2_rn(v0.x, v0.y);
    __half2 h1 = __floats2half2_rn(v0.z, v0.w);
    __half2 h2 = __floats2half2_rn(v1.x, v1.y);
    __half2 h3 = __floats2half2_rn(v1.z, v1.w);
    uint4 u;
    u.x = *(unsigned*)&h0; u.y = *(unsigned*)&h1;
    u.z = *(unsigned*)&h2; u.w = *(unsigned*)&h3;
    *reinterpret_cast<uint4*>(&g_xh[i]) = u;
}

// ---------------- transpose + convert Wi[k][n] -> g_wih[n][k] fp16 --------
__global__ void transp_wi_kernel(const float* __restrict__ Wi) {
    __shared__ __half tile[32][33];
    int n0 = blockIdx.x * 32;
    int k0 = blockIdx.y * 32;
    int tx = threadIdx.x, ty = threadIdx.y;
#pragma unroll
    for (int i = ty; i < 32; i += 8)
        tile[i][tx] = __float2half_rn(Wi[(size_t)(k0 + i) * GG + n0 + tx]);
    __syncthreads();
#pragma unroll
    for (int i = ty; i < 32; i += 8)
        g_wih[(size_t)(n0 + i) * VV + k0 + tx] = tile[tx][i];
}

// ---------------- Phase 1: fp16 mma.sync GEMM, 128x128x64, 256 threads ----
__global__ void __launch_bounds__(256) gemm_pre_tc(const float* __restrict__ bias) {
    extern __shared__ __half sm1[];
    __half* As[2] = { sm1,          sm1 + 18432 };
    __half* Bs[2] = { sm1 + 9216,   sm1 + 27648 };

    const int tid = threadIdx.x;
    const int w = tid >> 5, lane = tid & 31;
    const int m0blk = blockIdx.y * 128;
    const int n0blk = blockIdx.x * 128;
    const int wm = (w >> 2) * 64;
    const int wn = (w & 3) * 32;
    const int r = lane >> 2, kq = lane & 3;

    const int a_row = (lane & 7) + (lane & 8);
    const int a_k8  = (lane >> 4) << 3;
    const int b_nrow = (lane & 7) + ((lane >> 4) << 3);
    const int b_k8   = ((lane >> 3) & 1) << 3;

    float acc[16][4];
#pragma unroll
    for (int i = 0; i < 16; i++)
#pragma unroll
        for (int j = 0; j < 4; j++) acc[i][j] = 0.0f;

    const int lrow = tid >> 3, lc16 = (tid & 7) << 3;

#pragma unroll
    for (int q = 0; q < 4; ++q) {
        int row = lrow + q * 32;
        cp16(sptr(&As[0][row * 72 + lc16]), g_xh + (size_t)(m0blk + row) * VV + lc16);
        cp16(sptr(&Bs[0][row * 72 + lc16]), g_wih + (size_t)(n0blk + row) * VV + lc16);
    }
    cp_commit();

    const int NIT = VV / 64;
    for (int it = 0; it < NIT; ++it) {
        int nxt = it + 1;
        if (nxt < NIT) {
            int s = nxt & 1;
            int k0 = nxt * 64;
#pragma unroll
            for (int q = 0; q < 4; ++q) {
                int row = lrow + q * 32;
                cp16(sptr(&As[s][row * 72 + lc16]),
                     g_xh + (size_t)(m0blk + row) * VV + k0 + lc16);
                cp16(sptr(&Bs[s][row * 72 + lc16]),
                     g_wih + (size_t)(n0blk + row) * VV + k0 + lc16);
            }
            cp_commit();
            cp_wait<1>();
        } else {
            cp_wait<0>();
        }
        __syncthreads();

        const __half* Ab = As[it & 1];
        const __half* Bb = Bs[it & 1];
#pragma unroll
        for (int ks = 0; ks < 4; ++ks) {
            int kk = ks * 16;
            unsigned af[4][4];
#pragma unroll
            for (int mt = 0; mt < 4; ++mt)
                ldsm4(af[mt][0], af[mt][1], af[mt][2], af[mt][3],
                      sptr(Ab + (wm + mt * 16 + a_row) * 72 + kk + a_k8));
            unsigned bf[4][2];
            {
                unsigned q0, q1, q2, q3;
                ldsm4(q0, q1, q2, q3, sptr(Bb + (wn + b_nrow) * 72 + kk + b_k8));
                bf[0][0] = q0; bf[0][1] = q1; bf[1][0] = q2; bf[1][1] = q3;
                ldsm4(q0, q1, q2, q3, sptr(Bb + (wn + 16 + b_nrow) * 72 + kk + b_k8));
                bf[2][0] = q0; bf[2][1] = q1; bf[3][0] = q2; bf[3][1] = q3;
            }
#pragma unroll
            for (int mt = 0; mt < 4; ++mt)
#pragma unroll
                for (int nt = 0; nt < 4; ++nt)
                    mma_f16(acc[mt * 4 + nt],
                            af[mt][0], af[mt][1], af[mt][2], af[mt][3],
                            bf[nt][0], bf[nt][1]);
        }
        __syncthreads();
    }

#pragma unroll
    for (int mt = 0; mt < 4; ++mt) {
#pragma unroll
        for (int nt = 0; nt < 4; ++nt) {
            float* a = acc[mt * 4 + nt];
            int col = n0blk + wn + nt * 8 + 2 * kq;
            float b0 = __ldg(&bias[col]), b1 = __ldg(&bias[col + 1]);
            int row0 = m0blk + wm + mt * 16 + r;
            *reinterpret_cast<float2*>(&g_pre[(size_t)row0 * GG + col]) =
                make_float2(a[0] + b0, a[1] + b1);
            *reinterpret_cast<float2*>(&g_pre[(size_t)(row0 + 8) * GG + col]) =
                make_float2(a[2] + b0, a[3] + b1);
        }
    }
}

// ---------------- Phase 2: persistent recurrence (fp16) -------------------
// smem: sWh2 @0 (65536) | sH0 @65536 (66560) | sH1 @132096 (66560)
//       | sRed @198656 (8192) | sGpre @206848 (8192) | sEos @215040 (64)
#define SM_SH0  65536
#define SM_SH1  132096
#define SM_SRED 198656
#define SM_GPRE 206848
#define SM_EOS  215040
#define P2_SMEM 215104

__global__ void __launch_bounds__(256) lstm_recurrent(
        const float* __restrict__ Wh,
        const float* __restrict__ h0,
        const float* __restrict__ c0,
        const float* __restrict__ x,
        const unsigned char* __restrict__ eos0,
        float* __restrict__ out) {
    extern __shared__ unsigned char sm2[];
    uint2*  sWh2 = (uint2*)sm2;
    __half* sH[2] = { (__half*)(sm2 + SM_SH0), (__half*)(sm2 + SM_SH1) };
    float*  sRed  = (float*)(sm2 + SM_SRED);
    float*  sGpre = (float*)(sm2 + SM_GPRE);   // [64][32]: row*32 + g*8 + col
    unsigned char* sEos = sm2 + SM_EOS;

    const int tid = threadIdx.x;
    const int w = tid >> 5, lane = tid & 31;
    const int blk = blockIdx.x;
    const int j0 = blk * 8;

    // ---- prologue ----
    if (blk == 0) {  // eos prefix-OR into global
        unsigned char* flags = (unsigned char*)sRed;
        for (int i = tid; i < TT * BB; i += 256) {
            int t = i >> 6, b = i & 63;
            flags[i] = (x[((size_t)t * BB + b) * VV + EOS_ID] != 0.0f) ? 1 : 0;
        }
        __syncthreads();
        if (tid < BB) {
            unsigned char e = eos0[tid] ? 1 : 0;
            for (int t = 0; t < TT; ++t) {
                g_eos[t * BB + tid] = e;
                e |= flags[t * BB + tid];
            }
        }
        __syncthreads();
    }
    // Wh -> smem as pre-built B fragments: sWh2[g*2048 + kk16*32 + lane]
    for (int i = tid; i < 4 * 64 * 32; i += 256) {
        int t = i & 31;
        int kk = (i >> 5) & 63;
        int g = i >> 11;
        int k0 = kk * 16 + (t & 3) * 2;
        int n = t >> 2;
        const float* wp = Wh + (size_t)k0 * GG + g * HH + j0 + n;
        __half2 lo = __floats2half2_rn(wp[0], wp[GG]);
        __half2 hi = __floats2half2_rn(wp[8 * GG], wp[9 * GG]);
        sWh2[i] = make_uint2(*(unsigned*)&lo, *(unsigned*)&hi);
    }
    for (int i = tid; i < BB * 8; i += 256) {
        int b = i >> 3, n = i & 7;
        g_hbuf[0][b * HH + j0 + n] = __float2half_rn(h0[b * HH + j0 + n]);
        g_c[b * HH + j0 + n] = c0[b * HH + j0 + n];
    }
    grid_sync();

    const int half_w = w >> 2;
    const int mt = w & 3;
    const int m0 = mt * 16;
    const int r = lane >> 2;
    const int kq = lane & 3;
    const int a_row = (lane & 7) + (lane & 8);
    const int a_k8 = (lane >> 4) << 3;
    const int lrow = tid >> 2, lc16 = (tid & 3) << 3;

    for (int t = 0; t < TT; ++t) {
        const __half* hin = g_hbuf[t & 1];
        __half* hout = g_hbuf[(t + 1) & 1];
        const float* pre_t = g_pre + (size_t)t * BB * GG;

        // --- group A: g_pre slice + eos + h chunk 0 ---
        {
            // g_pre: 512 cp16 total, 2/thread. f -> row, gate, half
#pragma unroll
            for (int q = 0; q < 2; ++q) {
                int f = tid * 2 + q;
                int row = f >> 3;
                int seg = f & 7;
                int g = seg >> 1, hf = seg & 1;
                cp16(sptr(&sGpre[row * 32 + g * 8 + hf * 4]),
                     pre_t + (size_t)row * GG + g * HH + j0 + hf * 4);
            }
            if (tid < 4)
                cp16(sptr(sEos + tid * 16), g_eos + t * BB + tid * 16);
            __half* dst = sH[0];
#pragma unroll
            for (int q = 0; q < 16; ++q) {
                int col = lc16 + q * 32;
                cp16(sptr(&dst[lrow * 520 + col]), hin + (size_t)lrow * HH + col);
            }
            cp_commit();
        }
        // --- group B: h chunk 1 ---
        {
            __half* dst = sH[1];
            const __half* src = hin + 512;
#pragma unroll
            for (int q = 0; q < 16; ++q) {
                int col = lc16 + q * 32;
                cp16(sptr(&dst[lrow * 520 + col]), src + (size_t)lrow * HH + col);
            }
            cp_commit();
        }

        float acc[4][4];
#pragma unroll
        for (int g = 0; g < 4; ++g)
#pragma unroll
            for (int j = 0; j < 4; ++j) acc[g][j] = 0.0f;

#pragma unroll
        for (int c = 0; c < 2; ++c) {
            if (c == 0) cp_wait<1>(); else cp_wait<0>();
            __syncthreads();
            const __half* sh = sH[c];
#pragma unroll
            for (int ks = 0; ks < 16; ++ks) {
                int kloc = half_w * 256 + ks * 16;
                unsigned a0, a1, a2, a3;
                ldsm4(a0, a1, a2, a3, sptr(sh + (m0 + a_row) * 520 + kloc + a_k8));
                int kk16 = c * 32 + half_w * 16 + ks;
                const uint2* wb = sWh2 + kk16 * 32 + lane;
#pragma unroll
                for (int g = 0; g < 4; ++g) {
                    uint2 bb = wb[g * 2048];
                    mma_f16(acc[g], a0, a1, a2, a3, bb.x, bb.y);
                }
            }
            if (c == 0) __syncthreads();
        }

        __syncthreads();
        if (half_w == 1) {
#pragma unroll
            for (int g = 0; g < 4; ++g)
                *reinterpret_cast<float4*>(&sRed[((mt * 4 + g) * 32 + lane) * 4]) =
                    make_float4(acc[g][0], acc[g][1], acc[g][2], acc[g][3]);
        }
        __syncthreads();
        if (half_w == 0) {
#pragma unroll
            for (int g = 0; g < 4; ++g) {
                float4 v = *reinterpret_cast<float4*>(&sRed[((mt * 4 + g) * 32 + lane) * 4]);
                acc[g][0] += v.x; acc[g][1] += v.y; acc[g][2] += v.z; acc[g][3] += v.w;
            }
#pragma unroll
            for (int p = 0; p < 4; ++p) {
                int row = m0 + r + ((p >= 2) ? 8 : 0);
                int col = 2 * kq + (p & 1);
                int j = j0 + col;
                const float* gp = &sGpre[row * 32];
                float iv = acc[0][p] + gp[col];
                float fv = acc[1][p] + gp[8 + col];
                float gv = acc[2][p] + gp[16 + col];
                float ov = acc[3][p] + gp[24 + col];
                float cold = g_c[row * HH + j];
                float nc = sigf(fv) * cold + sigf(iv) * tanhf(gv);
                float nh = sigf(ov) * tanhf(nc);
                __stcg(&out[(size_t)t * BB * HH + row * HH + j], nh);
                unsigned char m = sEos[row];
                g_c[row * HH + j] = m ? cold : nc;
                __half hold = hin[row * HH + j];
                hout[row * HH + j] = m ? hold : __float2half_rn(nh);
            }
        }
        grid_sync();
    }
}

// ---------------- launch ----------------
extern "C" void kernel_launch(void* const* d_in, const int* in_sizes, int n_in,
                              void* d_out, int out_size) {
    const float* x    = (const float*)d_in[0];
    const float* Wi   = (const float*)d_in[1];
    const float* Wh   = (const float*)d_in[2];
    const float* bias = (const float*)d_in[3];
    const float* c0   = (const float*)d_in[4];
    const float* h0   = (const float*)d_in[5];
    const unsigned char* eos0 = (const unsigned char*)d_in[6];
    float* out = (float*)d_out;

    conv_x_kernel<<<(TT * BB * VV) / (256 * 8), 256>>>(x);
    transp_wi_kernel<<<dim3(GG / 32, VV / 32), dim3(32, 8)>>>(Wi);

    static int inited = 0;
    const int p1_smem = 4 * 9216 * 2;                 // 73728
    if (!inited) {
        cudaFuncSetAttribute(gemm_pre_tc,
                             cudaFuncAttributeMaxDynamicSharedMemorySize, p1_smem);
        cudaFuncSetAttribute(lstm_recurrent,
                             cudaFuncAttributeMaxDynamicSharedMemorySize, P2_SMEM);
        inited = 1;
    }
    gemm_pre_tc<<<dim3(GG / 128, (TT * BB) / 128), 256, p1_smem>>>(bias);
    lstm_recurrent<<<NBLK, 256, P2_SMEM>>>(Wh, h0, c0, x, eos0, out);
}